// round 2
// baseline (speedup 1.0000x reference)
#include <cuda_runtime.h>

#define NN 50000
#define NT 256
#define EMAX 4500000

// ---------------- scratch (static device globals; no allocs) ----------------
__device__ int   g_is64;                 // 1 if edge indices are int64, 0 if int32
__device__ int   g_cnt[6 * NN];          // [2r]=deg_out(src), [2r+1]=deg_in(dst)
__device__ int2  g_edges[EMAX];          // compacted (src + r*NN, dst + r*NN)
__device__ float g_h1 [3 * NN * 16];     // per-relation scaled layer-1 features
__device__ float g_m  [3 * NN * 16];     // per-relation aggregation buffers
__device__ float g_s  [3 * NN];          // per-relation scalar layer-2 messages
__device__ float g_o2 [3 * NN];          // per-relation scalar aggregation

// ---------------- dtype detection ----------------
// Indices are in [0, 50000): if stored little-endian int64, every odd 32-bit
// word is 0. If int32, the first 2048 odd words are random node ids.
__global__ void k_detect(const unsigned* __restrict__ p, int n) {
    __shared__ int found;
    if (threadIdx.x == 0) found = 0;
    __syncthreads();
    int f = 0;
    for (int i = threadIdx.x; i < n; i += blockDim.x)
        if (p[2 * i + 1] != 0u) f = 1;
    if (f) atomicOr(&found, 1);
    __syncthreads();
    if (threadIdx.x == 0) g_is64 = found ? 0 : 1;
}

__device__ __forceinline__ int ldidx(const void* __restrict__ p, int i) {
    return g_is64 ? (int)__ldg((const long long*)p + i)
                  : __ldg((const int*)p + i);
}

__device__ __forceinline__ float rs_of(int cnt) {
    return rsqrtf((float)(cnt > 0 ? cnt : 1));
}

// ---------------- zero counters ----------------
__global__ void k_zero_cnt() {
    int i = blockIdx.x * blockDim.x + threadIdx.x;
    if (i < 6 * NN) g_cnt[i] = 0;
}

// ---------------- degrees + index compaction (single pass over int64) -------
__global__ void k_degc(const void* __restrict__ src, const void* __restrict__ dst,
                       int E, int r, int eoff) {
    int e = blockIdx.x * blockDim.x + threadIdx.x;
    if (e >= E) return;
    int s = ldidx(src, e);
    int d = ldidx(dst, e);
    atomicAdd(&g_cnt[(2 * r)     * NN + s], 1);
    atomicAdd(&g_cnt[(2 * r + 1) * NN + d], 1);
    g_edges[eoff + e] = make_int2(r * NN + s, r * NN + d);
}

// ---------------- layer 1: per-node transform (and zero g_m) ----------------
__global__ void k_layer1_node(const float* __restrict__ x, const float* __restrict__ W1) {
    __shared__ float sW[3 * 32 * 16];
    for (int i = threadIdx.x; i < 1536; i += blockDim.x) sW[i] = W1[i];
    __syncthreads();
    int n = blockIdx.x * blockDim.x + threadIdx.x;
    if (n >= NN) return;
    float xv[32];
    #pragma unroll
    for (int j = 0; j < 8; j++) {
        float4 v = __ldg((const float4*)(x + (size_t)n * 32) + j);
        xv[4*j] = v.x; xv[4*j+1] = v.y; xv[4*j+2] = v.z; xv[4*j+3] = v.w;
    }
    #pragma unroll
    for (int r = 0; r < 3; r++) {
        float a = rs_of(g_cnt[(2 * r) * NN + n]);
        float y[16];
        #pragma unroll
        for (int f = 0; f < 16; f++) y[f] = 0.f;
        #pragma unroll
        for (int j = 0; j < 32; j++) {
            float xj = xv[j];
            #pragma unroll
            for (int f = 0; f < 16; f++)
                y[f] += xj * sW[r * 512 + j * 16 + f];
        }
        float* hp = &g_h1[(size_t)(r * NN + n) * 16];
        float* mp = &g_m [(size_t)(r * NN + n) * 16];
        #pragma unroll
        for (int f = 0; f < 16; f += 4) {
            *(float4*)(hp + f) = make_float4(a*y[f], a*y[f+1], a*y[f+2], a*y[f+3]);
            *(float4*)(mp + f) = make_float4(0.f, 0.f, 0.f, 0.f);
        }
    }
}

// ---------------- layer 1: edge scatter, 1 thread/edge, 4x red.v4 -----------
__global__ void k_scatter16(int Etot) {
    int e = blockIdx.x * blockDim.x + threadIdx.x;
    if (e >= Etot) return;
    int2 ed = g_edges[e];
    const float4* hp = (const float4*)&g_h1[(size_t)ed.x * 16];
    float*        mp = &g_m[(size_t)ed.y * 16];
    float4 v0 = __ldg(hp + 0);
    float4 v1 = __ldg(hp + 1);
    float4 v2 = __ldg(hp + 2);
    float4 v3 = __ldg(hp + 3);
    asm volatile("red.global.add.v4.f32 [%0], {%1, %2, %3, %4};"
                 :: "l"(mp + 0),  "f"(v0.x), "f"(v0.y), "f"(v0.z), "f"(v0.w) : "memory");
    asm volatile("red.global.add.v4.f32 [%0], {%1, %2, %3, %4};"
                 :: "l"(mp + 4),  "f"(v1.x), "f"(v1.y), "f"(v1.z), "f"(v1.w) : "memory");
    asm volatile("red.global.add.v4.f32 [%0], {%1, %2, %3, %4};"
                 :: "l"(mp + 8),  "f"(v2.x), "f"(v2.y), "f"(v2.z), "f"(v2.w) : "memory");
    asm volatile("red.global.add.v4.f32 [%0], {%1, %2, %3, %4};"
                 :: "l"(mp + 12), "f"(v3.x), "f"(v3.y), "f"(v3.z), "f"(v3.w) : "memory");
}

// ---------------- combine + relu + layer-2 node transform (zero g_o2) -------
__global__ void k_combine(const float* __restrict__ b1, const float* __restrict__ W2) {
    __shared__ float sW2[48], sb1[48];
    if (threadIdx.x < 48) {
        sW2[threadIdx.x] = W2[threadIdx.x];
        sb1[threadIdx.x] = b1[threadIdx.x];
    }
    __syncthreads();
    int n = blockIdx.x * blockDim.x + threadIdx.x;
    if (n >= NN) return;
    float acc[16];
    #pragma unroll
    for (int f = 0; f < 16; f++) acc[f] = 0.f;
    #pragma unroll
    for (int r = 0; r < 3; r++) {
        float ain = rs_of(g_cnt[(2 * r + 1) * NN + n]);
        const float* mp = &g_m[(size_t)(r * NN + n) * 16];
        #pragma unroll
        for (int f = 0; f < 16; f += 4) {
            float4 v = *(const float4*)(mp + f);
            acc[f]   += v.x * ain + sb1[r*16 + f];
            acc[f+1] += v.y * ain + sb1[r*16 + f + 1];
            acc[f+2] += v.z * ain + sb1[r*16 + f + 2];
            acc[f+3] += v.w * ain + sb1[r*16 + f + 3];
        }
    }
    #pragma unroll
    for (int f = 0; f < 16; f++) acc[f] = fmaxf(acc[f], 0.f);
    #pragma unroll
    for (int r = 0; r < 3; r++) {
        float aout = rs_of(g_cnt[(2 * r) * NN + n]);
        float dot = 0.f;
        #pragma unroll
        for (int f = 0; f < 16; f++) dot += acc[f] * sW2[r*16 + f];
        g_s [r * NN + n] = aout * dot;
        g_o2[r * NN + n] = 0.f;
    }
}

// ---------------- layer 2: scalar edge scatter ----------------
__global__ void k_scatter1(int Etot) {
    int e = blockIdx.x * blockDim.x + threadIdx.x;
    if (e >= Etot) return;
    int2 ed = g_edges[e];
    float v = __ldg(&g_s[ed.x]);
    atomicAdd(&g_o2[ed.y], v);
}

// ---------------- final ----------------
__global__ void k_final(float* __restrict__ out, const float* __restrict__ b2) {
    int n = blockIdx.x * blockDim.x + threadIdx.x;
    if (n >= NN) return;
    float o = 0.f;
    #pragma unroll
    for (int r = 0; r < 3; r++)
        o += g_o2[r * NN + n] * rs_of(g_cnt[(2 * r + 1) * NN + n]) + __ldg(b2 + r);
    out[n] = o;
}

// ---------------- host ----------------
extern "C" void kernel_launch(void* const* d_in, const int* in_sizes, int n_in,
                              void* d_out, int out_size) {
    const float* x  = (const float*)d_in[0];
    const void*  src[3] = { d_in[1], d_in[3], d_in[5] };
    const void*  dst[3] = { d_in[2], d_in[4], d_in[6] };
    int          E[3]   = { in_sizes[1], in_sizes[3], in_sizes[5] };
    const float* W1 = (const float*)d_in[7];
    const float* b1 = (const float*)d_in[8];
    const float* W2 = (const float*)d_in[9];
    const float* b2 = (const float*)d_in[10];
    float*       out = (float*)d_out;

    int Etot = E[0] + E[1] + E[2];
    if (Etot > EMAX) Etot = EMAX;  // safety; dataset fits

    int nprobe = E[0] < 2048 ? E[0] : 2048;
    k_detect<<<1, NT>>>((const unsigned*)d_in[1], nprobe);

    k_zero_cnt<<<(6 * NN + NT - 1) / NT, NT>>>();
    int eoff = 0;
    for (int r = 0; r < 3; r++) {
        k_degc<<<(E[r] + NT - 1) / NT, NT>>>(src[r], dst[r], E[r], r, eoff);
        eoff += E[r];
    }

    k_layer1_node<<<(NN + NT - 1) / NT, NT>>>(x, W1);
    k_scatter16<<<(Etot + NT - 1) / NT, NT>>>(Etot);

    k_combine<<<(NN + NT - 1) / NT, NT>>>(b1, W2);
    k_scatter1<<<(Etot + NT - 1) / NT, NT>>>(Etot);

    k_final<<<(NN + NT - 1) / NT, NT>>>(out, b2);
}

// round 3
// speedup vs baseline: 1.2462x; 1.2462x over previous
#include <cuda_runtime.h>

#define NN 50000
#define NT 256
#define EMAX 4500000

// ---------------- scratch (static device globals; no allocs) ----------------
__device__ int   g_is64;                 // 1 if edge indices are int64, 0 if int32
__device__ int   g_cnt[6 * NN];          // [2r]=deg_out(src), [2r+1]=deg_in(dst)
__device__ int2  g_edges[EMAX];          // compacted (src + r*NN, dst + r*NN)
__device__ float g_h1 [3 * NN * 16];     // per-relation scaled layer-1 features
__device__ float g_m  [3 * NN * 16];     // per-relation aggregation buffers
__device__ float g_s  [3 * NN];          // per-relation scalar layer-2 messages
__device__ float g_o2 [3 * NN];          // per-relation scalar aggregation

// ---------------- dtype detection ----------------
// Indices are in [0, 50000): if stored little-endian int64, every odd 32-bit
// word is 0. If int32, the first 2048 odd words are random node ids.
__global__ void k_detect(const unsigned* __restrict__ p, int n) {
    __shared__ int found;
    if (threadIdx.x == 0) found = 0;
    __syncthreads();
    int f = 0;
    for (int i = threadIdx.x; i < n; i += blockDim.x)
        if (p[2 * i + 1] != 0u) f = 1;
    if (f) atomicOr(&found, 1);
    __syncthreads();
    if (threadIdx.x == 0) g_is64 = found ? 0 : 1;
}

__device__ __forceinline__ int ldidx(const void* __restrict__ p, int i) {
    return g_is64 ? (int)__ldg((const long long*)p + i)
                  : __ldg((const int*)p + i);
}

__device__ __forceinline__ float rs_of(int cnt) {
    return rsqrtf((float)(cnt > 0 ? cnt : 1));
}

// ---------------- zero counters ----------------
__global__ void k_zero_cnt() {
    int i = blockIdx.x * blockDim.x + threadIdx.x;
    if (i < 6 * NN) g_cnt[i] = 0;
}

// ---------------- degrees + index compaction (single pass over int64) -------
__global__ void k_degc(const void* __restrict__ src, const void* __restrict__ dst,
                       int E, int r, int eoff) {
    int e = blockIdx.x * blockDim.x + threadIdx.x;
    if (e >= E) return;
    int s = ldidx(src, e);
    int d = ldidx(dst, e);
    atomicAdd(&g_cnt[(2 * r)     * NN + s], 1);
    atomicAdd(&g_cnt[(2 * r + 1) * NN + d], 1);
    g_edges[eoff + e] = make_int2(r * NN + s, r * NN + d);
}

// ---------------- layer 1: per-node transform (and zero g_m) ----------------
__global__ void k_layer1_node(const float* __restrict__ x, const float* __restrict__ W1) {
    __shared__ float sW[3 * 32 * 16];
    for (int i = threadIdx.x; i < 1536; i += blockDim.x) sW[i] = W1[i];
    __syncthreads();
    int n = blockIdx.x * blockDim.x + threadIdx.x;
    if (n >= NN) return;
    float xv[32];
    #pragma unroll
    for (int j = 0; j < 8; j++) {
        float4 v = __ldg((const float4*)(x + (size_t)n * 32) + j);
        xv[4*j] = v.x; xv[4*j+1] = v.y; xv[4*j+2] = v.z; xv[4*j+3] = v.w;
    }
    #pragma unroll
    for (int r = 0; r < 3; r++) {
        float a = rs_of(g_cnt[(2 * r) * NN + n]);
        float y[16];
        #pragma unroll
        for (int f = 0; f < 16; f++) y[f] = 0.f;
        #pragma unroll
        for (int j = 0; j < 32; j++) {
            float xj = xv[j];
            #pragma unroll
            for (int f = 0; f < 16; f++)
                y[f] += xj * sW[r * 512 + j * 16 + f];
        }
        float* hp = &g_h1[(size_t)(r * NN + n) * 16];
        float* mp = &g_m [(size_t)(r * NN + n) * 16];
        #pragma unroll
        for (int f = 0; f < 16; f += 4) {
            *(float4*)(hp + f) = make_float4(a*y[f], a*y[f+1], a*y[f+2], a*y[f+3]);
            *(float4*)(mp + f) = make_float4(0.f, 0.f, 0.f, 0.f);
        }
    }
}

// ---- layer 1: edge scatter, 4 threads/edge, 1 LDG.128 + 1 RED.128 each -----
__global__ void k_scatter16(int Etot) {
    long long t = (long long)blockIdx.x * blockDim.x + threadIdx.x;
    if (t >= (long long)Etot * 4) return;
    int e = (int)(t >> 2), c = (int)(t & 3);
    int2 ed = *(const int2*)&g_edges[e];          // same addr for 4 lanes: L1 broadcast
    const float4 v = __ldg((const float4*)&g_h1[(size_t)ed.x * 16] + c);
    float* mp = &g_m[(size_t)ed.y * 16 + c * 4];
    asm volatile("red.global.add.v4.f32 [%0], {%1, %2, %3, %4};"
                 :: "l"(mp), "f"(v.x), "f"(v.y), "f"(v.z), "f"(v.w) : "memory");
}

// ---------------- combine + relu + layer-2 node transform (zero g_o2) -------
__global__ void k_combine(const float* __restrict__ b1, const float* __restrict__ W2) {
    __shared__ float sW2[48], sb1[48];
    if (threadIdx.x < 48) {
        sW2[threadIdx.x] = W2[threadIdx.x];
        sb1[threadIdx.x] = b1[threadIdx.x];
    }
    __syncthreads();
    int n = blockIdx.x * blockDim.x + threadIdx.x;
    if (n >= NN) return;
    float acc[16];
    #pragma unroll
    for (int f = 0; f < 16; f++) acc[f] = 0.f;
    #pragma unroll
    for (int r = 0; r < 3; r++) {
        float ain = rs_of(g_cnt[(2 * r + 1) * NN + n]);
        const float* mp = &g_m[(size_t)(r * NN + n) * 16];
        #pragma unroll
        for (int f = 0; f < 16; f += 4) {
            float4 v = *(const float4*)(mp + f);
            acc[f]   += v.x * ain + sb1[r*16 + f];
            acc[f+1] += v.y * ain + sb1[r*16 + f + 1];
            acc[f+2] += v.z * ain + sb1[r*16 + f + 2];
            acc[f+3] += v.w * ain + sb1[r*16 + f + 3];
        }
    }
    #pragma unroll
    for (int f = 0; f < 16; f++) acc[f] = fmaxf(acc[f], 0.f);
    #pragma unroll
    for (int r = 0; r < 3; r++) {
        float aout = rs_of(g_cnt[(2 * r) * NN + n]);
        float dot = 0.f;
        #pragma unroll
        for (int f = 0; f < 16; f++) dot += acc[f] * sW2[r*16 + f];
        g_s [r * NN + n] = aout * dot;
        g_o2[r * NN + n] = 0.f;
    }
}

// ---------------- layer 2: scalar edge scatter ----------------
__global__ void k_scatter1(int Etot) {
    int e = blockIdx.x * blockDim.x + threadIdx.x;
    if (e >= Etot) return;
    int2 ed = __ldg((const int2*)&g_edges[e]);
    float v = __ldg(&g_s[ed.x]);
    atomicAdd(&g_o2[ed.y], v);
}

// ---------------- final ----------------
__global__ void k_final(float* __restrict__ out, const float* __restrict__ b2) {
    int n = blockIdx.x * blockDim.x + threadIdx.x;
    if (n >= NN) return;
    float o = 0.f;
    #pragma unroll
    for (int r = 0; r < 3; r++)
        o += g_o2[r * NN + n] * rs_of(g_cnt[(2 * r + 1) * NN + n]) + __ldg(b2 + r);
    out[n] = o;
}

// ---------------- host ----------------
extern "C" void kernel_launch(void* const* d_in, const int* in_sizes, int n_in,
                              void* d_out, int out_size) {
    const float* x  = (const float*)d_in[0];
    const void*  src[3] = { d_in[1], d_in[3], d_in[5] };
    const void*  dst[3] = { d_in[2], d_in[4], d_in[6] };
    int          E[3]   = { in_sizes[1], in_sizes[3], in_sizes[5] };
    const float* W1 = (const float*)d_in[7];
    const float* b1 = (const float*)d_in[8];
    const float* W2 = (const float*)d_in[9];
    const float* b2 = (const float*)d_in[10];
    float*       out = (float*)d_out;

    int Etot = E[0] + E[1] + E[2];
    if (Etot > EMAX) Etot = EMAX;  // safety; dataset fits

    int nprobe = E[0] < 2048 ? E[0] : 2048;
    k_detect<<<1, NT>>>((const unsigned*)d_in[1], nprobe);

    k_zero_cnt<<<(6 * NN + NT - 1) / NT, NT>>>();
    int eoff = 0;
    for (int r = 0; r < 3; r++) {
        k_degc<<<(E[r] + NT - 1) / NT, NT>>>(src[r], dst[r], E[r], r, eoff);
        eoff += E[r];
    }

    k_layer1_node<<<(NN + NT - 1) / NT, NT>>>(x, W1);
    {
        long long work = (long long)Etot * 4;
        int blocks = (int)((work + NT - 1) / NT);
        k_scatter16<<<blocks, NT>>>(Etot);
    }

    k_combine<<<(NN + NT - 1) / NT, NT>>>(b1, W2);
    k_scatter1<<<(Etot + NT - 1) / NT, NT>>>(Etot);

    k_final<<<(NN + NT - 1) / NT, NT>>>(out, b2);
}